// round 4
// baseline (speedup 1.0000x reference)
#include <cuda_runtime.h>

#define E_TOTAL 1600000
#define N_NODES 50000

#define FSCALE     0.17677669529663687f  // 1/sqrt(32)
#define FINV_SQRT3 0.57735026918962576f  // 1/sqrt(3)

__device__ int  g_counts[N_NODES];
__device__ int  g_cursor[N_NODES];
__device__ int  g_offsets[N_NODES + 1];
__device__ int2 g_edges[E_TOTAL];   // {edge_id, sender}

__global__ void k_zero_counts() {
    int i = blockIdx.x * blockDim.x + threadIdx.x;
    if (i < N_NODES) g_counts[i] = 0;
}

__global__ void k_count(const int* __restrict__ receivers) {
    int e = blockIdx.x * blockDim.x + threadIdx.x;
    if (e < E_TOTAL) atomicAdd(&g_counts[__ldg(&receivers[e])], 1);
}

// Single-block exclusive scan over 50K counts -> offsets, cursor
__global__ void k_scan() {
    __shared__ int ssum[1024];
    const int CH = (N_NODES + 1023) / 1024;  // 49
    int t = threadIdx.x;
    int base = t * CH;
    int s = 0;
    #pragma unroll 1
    for (int i = 0; i < CH; i++) {
        int idx = base + i;
        if (idx < N_NODES) s += g_counts[idx];
    }
    ssum[t] = s;
    __syncthreads();
    // Hillis-Steele inclusive scan
    for (int off = 1; off < 1024; off <<= 1) {
        int v = (t >= off) ? ssum[t - off] : 0;
        __syncthreads();
        ssum[t] += v;
        __syncthreads();
    }
    int run = (t > 0) ? ssum[t - 1] : 0;
    #pragma unroll 1
    for (int i = 0; i < CH; i++) {
        int idx = base + i;
        if (idx < N_NODES) {
            g_offsets[idx] = run;
            g_cursor[idx]  = run;
            run += g_counts[idx];
        }
    }
    if (t == 1023) g_offsets[N_NODES] = ssum[1023];
}

__global__ void k_fill(const int* __restrict__ senders,
                       const int* __restrict__ receivers) {
    int e = blockIdx.x * blockDim.x + threadIdx.x;
    if (e < E_TOTAL) {
        int pos = atomicAdd(&g_cursor[__ldg(&receivers[e])], 1);
        g_edges[pos] = make_int2(e, __ldg(&senders[e]));
    }
}

// One warp per node. Lane l (<24) owns output channels: scal[l], vec[l][0..2].
__global__ __launch_bounds__(256) void k_gather(
    const float*  __restrict__ node_feats,
    const float4* __restrict__ edge_features,
    const float*  __restrict__ radial,
    const float*  __restrict__ w1,
    const float*  __restrict__ w2,
    float*        __restrict__ out)
{
    int gwarp = (blockIdx.x * blockDim.x + threadIdx.x) >> 5;
    int lane  = threadIdx.x & 31;
    if (gwarp >= N_NODES) return;
    int node = gwarp;
    int mm = lane & 7;

    bool g0 = lane < 8;
    bool g1 = (lane >= 8) && (lane < 16);
    bool g2 = (lane >= 16) && (lane < 24);

    // Preload weights into registers (lane-private columns), fold scales in.
    int cA = (lane < 24) ? lane : (lane - 24);  // lanes 24-31: dummy valid index
    float sA = FSCALE * (g2 ? FINV_SQRT3 : 1.f);
    float w1c[8], w2A[8], w2B[8];
    #pragma unroll
    for (int j = 0; j < 8; j++) {
        w1c[j] = __ldg(&w1[j * 8 + mm]);
        w2A[j] = __ldg(&w2[j * 48 + cA]) * sA;
        w2B[j] = __ldg(&w2[j * 48 + 24 + cA]) * FSCALE;
    }
    float fS = g1 ? 1.f : 0.f;  // vec uses s⊗e1 only for rows 8..15

    int beg = g_offsets[node];
    int end = g_offsets[node + 1];

    float acc_s = 0.f, acc_v0 = 0.f, acc_v1 = 0.f, acc_v2 = 0.f;

    #pragma unroll 1
    for (int k = beg; k < end; k++) {
        int2 pk = g_edges[k];
        int eid = pk.x;
        int snd = pk.y;

        // sender row: coalesced 128B, lane l holds node_feats[snd*32+l]
        float x = __ldg(&node_feats[snd * 32 + lane]);

        // edge features (uniform broadcast load)
        float4 ef = __ldg(&edge_features[eid]);
        float e0 = ef.x, e1x = ef.y, e1y = ef.z, e1z = ef.w;

        // radial: 8 floats broadcast across lane groups
        float r = __ldg(&radial[eid * 8 + mm]);

        // hidden layer: lane j(<8) meaningful h_j (others duplicate)
        float hacc = 0.f;
        #pragma unroll
        for (int i = 0; i < 8; i++)
            hacc = fmaf(__shfl_sync(0xffffffffu, r, i), w1c[i], hacc);
        // swish
        float h = hacc * (1.f / (1.f + __expf(-hacc)));

        // output weights for this lane's two channels
        float wa = 0.f, wb = 0.f;
        #pragma unroll
        for (int j = 0; j < 8; j++) {
            float hj = __shfl_sync(0xffffffffu, h, j);
            wa = fmaf(hj, w2A[j], wa);
            wb = fmaf(hj, w2B[j], wb);
        }

        // route sender-row values this lane needs
        float s  = __shfl_sync(0xffffffffu, x, mm);
        float v0 = __shfl_sync(0xffffffffu, x, 8 + 3 * mm);
        float v1 = __shfl_sync(0xffffffffu, x, 9 + 3 * mm);
        float v2 = __shfl_sync(0xffffffffu, x, 10 + 3 * mm);

        // branch-free channel math
        float eS   = g0 ? 1.f : (g1 ? e0 : 0.f);
        float dsel = g2 ? 1.f : 0.f;
        float dot  = fmaf(v0, e1x, fmaf(v1, e1y, v2 * e1z));
        float scal_inner = fmaf(s, eS, dot * dsel);

        float fV  = g0 ? 1.f : (g2 ? e0 : 0.f);
        float sfs = s * fS;
        float i0 = fmaf(v0, fV, sfs * e1x);
        float i1 = fmaf(v1, fV, sfs * e1y);
        float i2 = fmaf(v2, fV, sfs * e1z);

        acc_s  = fmaf(scal_inner, wa, acc_s);
        acc_v0 = fmaf(i0, wb, acc_v0);
        acc_v1 = fmaf(i1, wb, acc_v1);
        acc_v2 = fmaf(i2, wb, acc_v2);
    }

    if (lane < 24) {
        float* op = out + (size_t)node * 96;
        op[lane]              = acc_s;
        op[24 + 3 * lane]     = acc_v0;
        op[24 + 3 * lane + 1] = acc_v1;
        op[24 + 3 * lane + 2] = acc_v2;
    }
}

extern "C" void kernel_launch(void* const* d_in, const int* in_sizes, int n_in,
                              void* d_out, int out_size) {
    const float*  node_feats    = (const float*)d_in[0];
    const float4* edge_features = (const float4*)d_in[1];
    const float*  radial        = (const float*)d_in[2];
    const float*  w1            = (const float*)d_in[3];
    const float*  w2            = (const float*)d_in[4];
    const int*    senders       = (const int*)d_in[5];
    const int*    receivers     = (const int*)d_in[6];
    float* out = (float*)d_out;

    k_zero_counts<<<(N_NODES + 511) / 512, 512>>>();
    k_count<<<(E_TOTAL + 511) / 512, 512>>>(receivers);
    k_scan<<<1, 1024>>>();
    k_fill<<<(E_TOTAL + 511) / 512, 512>>>(senders, receivers);

    int gwarps  = N_NODES;                  // one warp per node
    int gblocks = (gwarps * 32 + 255) / 256;
    k_gather<<<gblocks, 256>>>(node_feats, edge_features, radial, w1, w2, out);
}

// round 6
// speedup vs baseline: 1.2697x; 1.2697x over previous
#include <cuda_runtime.h>

#define E_TOTAL 1600000
#define N_NODES 50000

#define FSCALE     0.17677669529663687f  // 1/sqrt(32)
#define FINV_SQRT3 0.57735026918962576f  // 1/sqrt(3)

__device__ int   g_counts[N_NODES];
__device__ int   g_cursor[N_NODES];
__device__ int   g_offsets[N_NODES + 1];
__device__ int2  g_edges[E_TOTAL];           // {edge_id, sender}
__device__ float g_w[(size_t)E_TOTAL * 48];  // per-edge folded weights

__global__ void k_zero_counts() {
    int i = blockIdx.x * blockDim.x + threadIdx.x;
    if (i < N_NODES) g_counts[i] = 0;
}

__global__ void k_count(const int* __restrict__ receivers) {
    int e = blockIdx.x * blockDim.x + threadIdx.x;
    if (e < E_TOTAL) atomicAdd(&g_counts[__ldg(&receivers[e])], 1);
}

__global__ void k_scan() {
    __shared__ int ssum[1024];
    const int CH = (N_NODES + 1023) / 1024;  // 49
    int t = threadIdx.x;
    int base = t * CH;
    int s = 0;
    #pragma unroll 1
    for (int i = 0; i < CH; i++) {
        int idx = base + i;
        if (idx < N_NODES) s += g_counts[idx];
    }
    ssum[t] = s;
    __syncthreads();
    for (int off = 1; off < 1024; off <<= 1) {
        int v = (t >= off) ? ssum[t - off] : 0;
        __syncthreads();
        ssum[t] += v;
        __syncthreads();
    }
    int run = (t > 0) ? ssum[t - 1] : 0;
    #pragma unroll 1
    for (int i = 0; i < CH; i++) {
        int idx = base + i;
        if (idx < N_NODES) {
            g_offsets[idx] = run;
            g_cursor[idx]  = run;
            run += g_counts[idx];
        }
    }
    if (t == 1023) g_offsets[N_NODES] = ssum[1023];
}

__global__ void k_fill(const int* __restrict__ senders,
                       const int* __restrict__ receivers) {
    int e = blockIdx.x * blockDim.x + threadIdx.x;
    if (e < E_TOTAL) {
        int pos = atomicAdd(&g_cursor[__ldg(&receivers[e])], 1);
        g_edges[pos] = make_int2(e, __ldg(&senders[e]));
    }
}

// Edge-parallel: w = swish(r@w1)@w2 with scales folded, streamed out.
__global__ __launch_bounds__(256) void k_weights(
    const float4* __restrict__ radial,
    const float*  __restrict__ w1,
    const float*  __restrict__ w2)
{
    __shared__ float sw1[64];
    __shared__ float sw2[384];
    int t = threadIdx.x;
    if (t < 64) sw1[t] = w1[t];
    for (int i = t; i < 384; i += 256) sw2[i] = w2[i];
    __syncthreads();

    int e = blockIdx.x * 256 + t;
    if (e >= E_TOTAL) return;

    float4 r0 = radial[2 * e];
    float4 r1 = radial[2 * e + 1];
    float r[8] = {r0.x, r0.y, r0.z, r0.w, r1.x, r1.y, r1.z, r1.w};

    float h[8];
    #pragma unroll
    for (int j = 0; j < 8; j++) {
        float acc = 0.f;
        #pragma unroll
        for (int i = 0; i < 8; i++) acc = fmaf(r[i], sw1[i * 8 + j], acc);
        h[j] = acc * (1.f / (1.f + __expf(-acc)));
    }

    float4* outw = (float4*)(g_w + (size_t)e * 48);
    #pragma unroll
    for (int c4 = 0; c4 < 12; c4++) {
        float o[4];
        #pragma unroll
        for (int u = 0; u < 4; u++) {
            int c = c4 * 4 + u;
            float acc = 0.f;
            #pragma unroll
            for (int j = 0; j < 8; j++) acc = fmaf(h[j], sw2[j * 48 + c], acc);
            float sc = (c >= 16 && c < 24) ? (FSCALE * FINV_SQRT3) : FSCALE;
            o[u] = acc * sc;
        }
        outw[c4] = make_float4(o[0], o[1], o[2], o[3]);
    }
}

// One block (128 thr = 4 warps) per node; each warp handles 1/4 of the segment.
// Lane l (<24) owns channels scal[l] and vec[l][0..2]. No shuffles, no atomics.
__global__ __launch_bounds__(128) void k_gather(
    const float*  __restrict__ node_feats,
    const float4* __restrict__ edge_features,
    float*        __restrict__ out)
{
    __shared__ float red[4][96];

    int node = blockIdx.x;
    int lane = threadIdx.x & 31;
    int wi   = threadIdx.x >> 5;
    int mm   = lane & 7;

    bool g0 = lane < 8;
    bool g1 = (lane >= 8) && (lane < 16);
    bool g2 = (lane >= 16) && (lane < 24);
    int  cA = (lane < 24) ? lane : 0;
    float fS = g1 ? 1.f : 0.f;

    int beg = g_offsets[node];
    int end = g_offsets[node + 1];
    int len = end - beg;
    int lo  = beg + (len * wi)     / 4;
    int hi  = beg + (len * (wi+1)) / 4;

    float acc_s = 0.f, acc_v0 = 0.f, acc_v1 = 0.f, acc_v2 = 0.f;

    int2 pk = (lo < hi) ? g_edges[lo] : make_int2(0, 0);
    #pragma unroll 1
    for (int k = lo; k < hi; k++) {
        int eid = pk.x;
        int snd = pk.y;
        if (k + 1 < hi) pk = g_edges[k + 1];

        const float* nf = node_feats + snd * 32;
        float s  = __ldg(nf + mm);
        float v0 = __ldg(nf + 8  + 3 * mm);
        float v1 = __ldg(nf + 9  + 3 * mm);
        float v2 = __ldg(nf + 10 + 3 * mm);

        float4 ef = __ldg(&edge_features[eid]);
        float e0 = ef.x, e1x = ef.y, e1y = ef.z, e1z = ef.w;

        const float* wp = g_w + (size_t)eid * 48;
        float wa = __ldg(wp + cA);
        float wb = __ldg(wp + 24 + cA);

        float eS   = g0 ? 1.f : (g1 ? e0 : 0.f);
        float dsel = g2 ? 1.f : 0.f;
        float dot  = fmaf(v0, e1x, fmaf(v1, e1y, v2 * e1z));
        float scal_inner = fmaf(s, eS, dot * dsel);

        float fV  = g0 ? 1.f : (g2 ? e0 : 0.f);
        float sfs = s * fS;
        float i0 = fmaf(v0, fV, sfs * e1x);
        float i1 = fmaf(v1, fV, sfs * e1y);
        float i2 = fmaf(v2, fV, sfs * e1z);

        acc_s  = fmaf(scal_inner, wa, acc_s);
        acc_v0 = fmaf(i0, wb, acc_v0);
        acc_v1 = fmaf(i1, wb, acc_v1);
        acc_v2 = fmaf(i2, wb, acc_v2);
    }

    if (lane < 24) {
        red[wi][lane]              = acc_s;
        red[wi][24 + 3 * lane]     = acc_v0;
        red[wi][24 + 3 * lane + 1] = acc_v1;
        red[wi][24 + 3 * lane + 2] = acc_v2;
    }
    __syncthreads();

    int t = threadIdx.x;
    if (t < 96) {
        float sum = red[0][t] + red[1][t] + red[2][t] + red[3][t];
        out[(size_t)node * 96 + t] = sum;
    }
}

extern "C" void kernel_launch(void* const* d_in, const int* in_sizes, int n_in,
                              void* d_out, int out_size) {
    const float*  node_feats    = (const float*)d_in[0];
    const float4* edge_features = (const float4*)d_in[1];
    const float4* radial        = (const float4*)d_in[2];
    const float*  w1            = (const float*)d_in[3];
    const float*  w2            = (const float*)d_in[4];
    const int*    senders       = (const int*)d_in[5];
    const int*    receivers     = (const int*)d_in[6];
    float* out = (float*)d_out;

    k_zero_counts<<<(N_NODES + 511) / 512, 512>>>();
    k_count<<<(E_TOTAL + 511) / 512, 512>>>(receivers);
    k_scan<<<1, 1024>>>();
    k_fill<<<(E_TOTAL + 511) / 512, 512>>>(senders, receivers);

    k_weights<<<(E_TOTAL + 255) / 256, 256>>>(edge_features ? (const float4*)d_in[2] : nullptr, w1, w2);
    k_gather<<<N_NODES, 128>>>(node_feats, edge_features, out);
}

// round 7
// speedup vs baseline: 1.2837x; 1.0111x over previous
#include <cuda_runtime.h>

#define E_TOTAL 1600000
#define N_NODES 50000

#define FSCALE     0.17677669529663687f  // 1/sqrt(32)
#define FINV_SQRT3 0.57735026918962576f  // 1/sqrt(3)

__device__ int    g_counts[N_NODES];
__device__ int    g_cursor[N_NODES];
__device__ int    g_offsets[N_NODES + 1];
__device__ int2   g_edges[E_TOTAL];            // slot -> {edge_id, sender}
__device__ float  g_wslot[(size_t)E_TOTAL * 48];  // slot-ordered folded weights
__device__ float4 g_efslot[E_TOTAL];           // slot-ordered edge features

__global__ void k_zero_counts() {
    int i = blockIdx.x * blockDim.x + threadIdx.x;
    if (i < N_NODES) g_counts[i] = 0;
}

__global__ void k_count(const int* __restrict__ receivers) {
    int e = blockIdx.x * blockDim.x + threadIdx.x;
    if (e < E_TOTAL) atomicAdd(&g_counts[__ldg(&receivers[e])], 1);
}

__global__ void k_scan() {
    __shared__ int ssum[1024];
    const int CH = (N_NODES + 1023) / 1024;  // 49
    int t = threadIdx.x;
    int base = t * CH;
    int s = 0;
    #pragma unroll 1
    for (int i = 0; i < CH; i++) {
        int idx = base + i;
        if (idx < N_NODES) s += g_counts[idx];
    }
    ssum[t] = s;
    __syncthreads();
    for (int off = 1; off < 1024; off <<= 1) {
        int v = (t >= off) ? ssum[t - off] : 0;
        __syncthreads();
        ssum[t] += v;
        __syncthreads();
    }
    int run = (t > 0) ? ssum[t - 1] : 0;
    #pragma unroll 1
    for (int i = 0; i < CH; i++) {
        int idx = base + i;
        if (idx < N_NODES) {
            g_offsets[idx] = run;
            g_cursor[idx]  = run;
            run += g_counts[idx];
        }
    }
    if (t == 1023) g_offsets[N_NODES] = ssum[1023];
}

__global__ void k_fill(const int* __restrict__ senders,
                       const int* __restrict__ receivers) {
    int e = blockIdx.x * blockDim.x + threadIdx.x;
    if (e < E_TOTAL) {
        int pos = atomicAdd(&g_cursor[__ldg(&receivers[e])], 1);
        g_edges[pos] = make_int2(e, __ldg(&senders[e]));
    }
}

// Slot-parallel: thread k computes w(48) for the edge at CSR slot k and
// writes w + edge_features into slot-ordered scratch. All writes coalesced.
__global__ __launch_bounds__(256) void k_weights(
    const float4* __restrict__ radial,
    const float4* __restrict__ edge_features,
    const float*  __restrict__ w1,
    const float*  __restrict__ w2)
{
    __shared__ float sw1[64];
    __shared__ float sw2[384];
    int t = threadIdx.x;
    if (t < 64) sw1[t] = w1[t];
    for (int i = t; i < 384; i += 256) sw2[i] = w2[i];
    __syncthreads();

    int k = blockIdx.x * 256 + t;
    if (k >= E_TOTAL) return;

    int eid = g_edges[k].x;

    g_efslot[k] = __ldg(&edge_features[eid]);

    float4 r0 = __ldg(&radial[2 * eid]);
    float4 r1 = __ldg(&radial[2 * eid + 1]);
    float r[8] = {r0.x, r0.y, r0.z, r0.w, r1.x, r1.y, r1.z, r1.w};

    float h[8];
    #pragma unroll
    for (int j = 0; j < 8; j++) {
        float acc = 0.f;
        #pragma unroll
        for (int i = 0; i < 8; i++) acc = fmaf(r[i], sw1[i * 8 + j], acc);
        h[j] = acc * (1.f / (1.f + __expf(-acc)));
    }

    float4* outw = (float4*)(g_wslot + (size_t)k * 48);
    #pragma unroll
    for (int c4 = 0; c4 < 12; c4++) {
        float o[4];
        #pragma unroll
        for (int u = 0; u < 4; u++) {
            int c = c4 * 4 + u;
            float acc = 0.f;
            #pragma unroll
            for (int j = 0; j < 8; j++) acc = fmaf(h[j], sw2[j * 48 + c], acc);
            float sc = (c >= 16 && c < 24) ? (FSCALE * FINV_SQRT3) : FSCALE;
            o[u] = acc * sc;
        }
        outw[c4] = make_float4(o[0], o[1], o[2], o[3]);
    }
}

// One block (4 warps) per node, warp takes 1/4 of the segment.
// All streams sequential except the node-row gather (L2-resident).
#define EDGE_BODY(KK)                                                         \
    {                                                                         \
        int2 pk = g_edges[(KK)];                                              \
        int snd = pk.y;                                                       \
        const float* nf = node_feats + snd * 32;                              \
        float s  = __ldg(nf + mm);                                            \
        float v0 = __ldg(nf + 8  + 3 * mm);                                   \
        float v1 = __ldg(nf + 9  + 3 * mm);                                   \
        float v2 = __ldg(nf + 10 + 3 * mm);                                   \
        float4 ef = g_efslot[(KK)];                                           \
        float e0 = ef.x, e1x = ef.y, e1y = ef.z, e1z = ef.w;                  \
        const float* wp = g_wslot + (size_t)(KK) * 48;                        \
        float wa = wp[cA];                                                    \
        float wb = wp[24 + cA];                                               \
        float eS   = g0 ? 1.f : (g1 ? e0 : 0.f);                              \
        float dsel = g2 ? 1.f : 0.f;                                          \
        float dot  = fmaf(v0, e1x, fmaf(v1, e1y, v2 * e1z));                  \
        float scal_inner = fmaf(s, eS, dot * dsel);                           \
        float fV  = g0 ? 1.f : (g2 ? e0 : 0.f);                               \
        float sfs = s * fS;                                                   \
        float i0 = fmaf(v0, fV, sfs * e1x);                                   \
        float i1 = fmaf(v1, fV, sfs * e1y);                                   \
        float i2 = fmaf(v2, fV, sfs * e1z);                                   \
        acc_s  = fmaf(scal_inner, wa, acc_s);                                 \
        acc_v0 = fmaf(i0, wb, acc_v0);                                        \
        acc_v1 = fmaf(i1, wb, acc_v1);                                        \
        acc_v2 = fmaf(i2, wb, acc_v2);                                        \
    }

__global__ __launch_bounds__(128) void k_gather(
    const float* __restrict__ node_feats,
    float*       __restrict__ out)
{
    __shared__ float red[4][96];

    int node = blockIdx.x;
    int lane = threadIdx.x & 31;
    int wi   = threadIdx.x >> 5;
    int mm   = lane & 7;

    bool g0 = lane < 8;
    bool g1 = (lane >= 8) && (lane < 16);
    bool g2 = (lane >= 16) && (lane < 24);
    int  cA = (lane < 24) ? lane : 0;
    float fS = g1 ? 1.f : 0.f;

    int beg = g_offsets[node];
    int end = g_offsets[node + 1];
    int len = end - beg;
    int lo  = beg + (len * wi)       / 4;
    int hi  = beg + (len * (wi + 1)) / 4;

    float acc_s = 0.f, acc_v0 = 0.f, acc_v1 = 0.f, acc_v2 = 0.f;

    int k = lo;
    #pragma unroll 1
    for (; k + 1 < hi; k += 2) {
        EDGE_BODY(k)
        EDGE_BODY(k + 1)
    }
    if (k < hi) EDGE_BODY(k)

    if (lane < 24) {
        red[wi][lane]              = acc_s;
        red[wi][24 + 3 * lane]     = acc_v0;
        red[wi][24 + 3 * lane + 1] = acc_v1;
        red[wi][24 + 3 * lane + 2] = acc_v2;
    }
    __syncthreads();

    int t = threadIdx.x;
    if (t < 96) {
        out[(size_t)node * 96 + t] = red[0][t] + red[1][t] + red[2][t] + red[3][t];
    }
}

extern "C" void kernel_launch(void* const* d_in, const int* in_sizes, int n_in,
                              void* d_out, int out_size) {
    const float*  node_feats    = (const float*)d_in[0];
    const float4* edge_features = (const float4*)d_in[1];
    const float4* radial        = (const float4*)d_in[2];
    const float*  w1            = (const float*)d_in[3];
    const float*  w2            = (const float*)d_in[4];
    const int*    senders       = (const int*)d_in[5];
    const int*    receivers     = (const int*)d_in[6];
    float* out = (float*)d_out;

    k_zero_counts<<<(N_NODES + 511) / 512, 512>>>();
    k_count<<<(E_TOTAL + 511) / 512, 512>>>(receivers);
    k_scan<<<1, 1024>>>();
    k_fill<<<(E_TOTAL + 511) / 512, 512>>>(senders, receivers);

    k_weights<<<(E_TOTAL + 255) / 256, 256>>>(radial, edge_features, w1, w2);
    k_gather<<<N_NODES, 128>>>(node_feats, out);
}

// round 8
// speedup vs baseline: 1.3402x; 1.0440x over previous
#include <cuda_runtime.h>

#define E_TOTAL 1600000
#define N_NODES 50000

#define FSCALE     0.17677669529663687f  // 1/sqrt(32)
#define FINV_SQRT3 0.57735026918962576f  // 1/sqrt(3)

__device__ int    g_counts[N_NODES];
__device__ int    g_cursor[N_NODES];
__device__ int    g_offsets[N_NODES + 1];
__device__ int2   g_edges[E_TOTAL];             // slot -> {edge_id, sender}
__device__ float4 g_hslot[(size_t)E_TOTAL * 2]; // slot-ordered hidden acts (x FSCALE)
__device__ float4 g_efslot[E_TOTAL];            // slot-ordered edge features

__global__ void k_zero_counts() {
    int i = blockIdx.x * blockDim.x + threadIdx.x;
    if (i < N_NODES) g_counts[i] = 0;
}

__global__ void k_count(const int* __restrict__ receivers) {
    int e = blockIdx.x * blockDim.x + threadIdx.x;
    if (e < E_TOTAL) atomicAdd(&g_counts[__ldg(&receivers[e])], 1);
}

__global__ void k_scan() {
    __shared__ int ssum[1024];
    const int CH = (N_NODES + 1023) / 1024;  // 49
    int t = threadIdx.x;
    int base = t * CH;
    int s = 0;
    #pragma unroll
    for (int i = 0; i < CH; i++) {           // unrolled: 49 loads in flight
        int idx = base + i;
        s += (idx < N_NODES) ? __ldg(&g_counts[idx]) : 0;
    }
    ssum[t] = s;
    __syncthreads();
    for (int off = 1; off < 1024; off <<= 1) {
        int v = (t >= off) ? ssum[t - off] : 0;
        __syncthreads();
        ssum[t] += v;
        __syncthreads();
    }
    int run = (t > 0) ? ssum[t - 1] : 0;
    int c[CH];
    #pragma unroll
    for (int i = 0; i < CH; i++) {
        int idx = base + i;
        c[i] = (idx < N_NODES) ? __ldg(&g_counts[idx]) : 0;
    }
    #pragma unroll
    for (int i = 0; i < CH; i++) {
        int idx = base + i;
        if (idx < N_NODES) {
            g_offsets[idx] = run;
            g_cursor[idx]  = run;
            run += c[i];
        }
    }
    if (t == 1023) g_offsets[N_NODES] = ssum[1023];
}

__global__ void k_fill(const int* __restrict__ senders,
                       const int* __restrict__ receivers) {
    int e = blockIdx.x * blockDim.x + threadIdx.x;
    if (e < E_TOTAL) {
        int pos = atomicAdd(&g_cursor[__ldg(&receivers[e])], 1);
        g_edges[pos] = make_int2(e, __ldg(&senders[e]));
    }
}

// Slot-parallel: thread k computes h(8) = swish(radial[eid]@w1)*FSCALE for the
// edge at CSR slot k; writes h + edge_features slot-ordered (coalesced).
__global__ __launch_bounds__(256) void k_hidden(
    const float4* __restrict__ radial,
    const float4* __restrict__ edge_features,
    const float*  __restrict__ w1)
{
    __shared__ float sw1[64];
    int t = threadIdx.x;
    if (t < 64) sw1[t] = w1[t];
    __syncthreads();

    int k = blockIdx.x * 256 + t;
    if (k >= E_TOTAL) return;

    int eid = g_edges[k].x;

    g_efslot[k] = __ldg(&edge_features[eid]);

    float4 r0 = __ldg(&radial[2 * eid]);
    float4 r1 = __ldg(&radial[2 * eid + 1]);
    float r[8] = {r0.x, r0.y, r0.z, r0.w, r1.x, r1.y, r1.z, r1.w};

    float h[8];
    #pragma unroll
    for (int j = 0; j < 8; j++) {
        float acc = 0.f;
        #pragma unroll
        for (int i = 0; i < 8; i++) acc = fmaf(r[i], sw1[i * 8 + j], acc);
        h[j] = acc * (FSCALE / (1.f + __expf(-acc)));
    }
    g_hslot[2 * k]     = make_float4(h[0], h[1], h[2], h[3]);
    g_hslot[2 * k + 1] = make_float4(h[4], h[5], h[6], h[7]);
}

// One block (4 warps) per node, warp takes 1/4 of the segment.
// Lane l (<24) owns channels scal[l], vec[l][0..2]. Weights recomputed from h.
#define EDGE_BODY(KK)                                                         \
    {                                                                         \
        int2 pk = g_edges[(KK)];                                              \
        int snd = pk.y;                                                       \
        const float* nf = node_feats + snd * 32;                              \
        float s  = __ldg(nf + mm);                                            \
        float v0 = __ldg(nf + 8  + 3 * mm);                                   \
        float v1 = __ldg(nf + 9  + 3 * mm);                                   \
        float v2 = __ldg(nf + 10 + 3 * mm);                                   \
        float4 ef = g_efslot[(KK)];                                           \
        float4 h0 = g_hslot[2 * (KK)];                                        \
        float4 h1 = g_hslot[2 * (KK) + 1];                                    \
        float e0 = ef.x, e1x = ef.y, e1y = ef.z, e1z = ef.w;                  \
        float wa, wb;                                                         \
        wa = fmaf(h0.x, w2A[0], fmaf(h0.y, w2A[1],                            \
             fmaf(h0.z, w2A[2], h0.w * w2A[3])));                             \
        wa = fmaf(h1.x, w2A[4], fmaf(h1.y, w2A[5],                            \
             fmaf(h1.z, w2A[6], fmaf(h1.w, w2A[7], wa))));                    \
        wb = fmaf(h0.x, w2B[0], fmaf(h0.y, w2B[1],                            \
             fmaf(h0.z, w2B[2], h0.w * w2B[3])));                             \
        wb = fmaf(h1.x, w2B[4], fmaf(h1.y, w2B[5],                            \
             fmaf(h1.z, w2B[6], fmaf(h1.w, w2B[7], wb))));                    \
        float eS   = g0 ? 1.f : (g1 ? e0 : 0.f);                              \
        float dsel = g2 ? 1.f : 0.f;                                          \
        float dot  = fmaf(v0, e1x, fmaf(v1, e1y, v2 * e1z));                  \
        float scal_inner = fmaf(s, eS, dot * dsel);                           \
        float fV  = g0 ? 1.f : (g2 ? e0 : 0.f);                               \
        float sfs = s * fS;                                                   \
        float i0 = fmaf(v0, fV, sfs * e1x);                                   \
        float i1 = fmaf(v1, fV, sfs * e1y);                                   \
        float i2 = fmaf(v2, fV, sfs * e1z);                                   \
        acc_s  = fmaf(scal_inner, wa, acc_s);                                 \
        acc_v0 = fmaf(i0, wb, acc_v0);                                        \
        acc_v1 = fmaf(i1, wb, acc_v1);                                        \
        acc_v2 = fmaf(i2, wb, acc_v2);                                        \
    }

__global__ __launch_bounds__(128) void k_gather(
    const float* __restrict__ node_feats,
    const float* __restrict__ w2,
    float*       __restrict__ out)
{
    __shared__ float red[4][96];

    int node = blockIdx.x;
    int lane = threadIdx.x & 31;
    int wi   = threadIdx.x >> 5;
    int mm   = lane & 7;

    bool g0 = lane < 8;
    bool g1 = (lane >= 8) && (lane < 16);
    bool g2 = (lane >= 16) && (lane < 24);
    int  cA = (lane < 24) ? lane : 0;
    float fS = g1 ? 1.f : 0.f;
    float sA = g2 ? FINV_SQRT3 : 1.f;

    float w2A[8], w2B[8];
    #pragma unroll
    for (int j = 0; j < 8; j++) {
        w2A[j] = __ldg(&w2[j * 48 + cA]) * sA;
        w2B[j] = __ldg(&w2[j * 48 + 24 + cA]);
    }

    int beg = g_offsets[node];
    int end = g_offsets[node + 1];
    int len = end - beg;
    int lo  = beg + (len * wi)       / 4;
    int hi  = beg + (len * (wi + 1)) / 4;

    float acc_s = 0.f, acc_v0 = 0.f, acc_v1 = 0.f, acc_v2 = 0.f;

    int k = lo;
    #pragma unroll 1
    for (; k + 1 < hi; k += 2) {
        EDGE_BODY(k)
        EDGE_BODY(k + 1)
    }
    if (k < hi) EDGE_BODY(k)

    if (lane < 24) {
        red[wi][lane]              = acc_s;
        red[wi][24 + 3 * lane]     = acc_v0;
        red[wi][24 + 3 * lane + 1] = acc_v1;
        red[wi][24 + 3 * lane + 2] = acc_v2;
    }
    __syncthreads();

    int t = threadIdx.x;
    if (t < 96) {
        out[(size_t)node * 96 + t] = red[0][t] + red[1][t] + red[2][t] + red[3][t];
    }
}

extern "C" void kernel_launch(void* const* d_in, const int* in_sizes, int n_in,
                              void* d_out, int out_size) {
    const float*  node_feats    = (const float*)d_in[0];
    const float4* edge_features = (const float4*)d_in[1];
    const float4* radial        = (const float4*)d_in[2];
    const float*  w1            = (const float*)d_in[3];
    const float*  w2            = (const float*)d_in[4];
    const int*    senders       = (const int*)d_in[5];
    const int*    receivers     = (const int*)d_in[6];
    float* out = (float*)d_out;

    k_zero_counts<<<(N_NODES + 511) / 512, 512>>>();
    k_count<<<(E_TOTAL + 511) / 512, 512>>>(receivers);
    k_scan<<<1, 1024>>>();
    k_fill<<<(E_TOTAL + 511) / 512, 512>>>(senders, receivers);

    k_hidden<<<(E_TOTAL + 255) / 256, 256>>>(radial, edge_features, w1);
    k_gather<<<N_NODES, 128>>>(node_feats, w2, out);
}

// round 9
// speedup vs baseline: 2.1001x; 1.5669x over previous
#include <cuda_runtime.h>

#define E_TOTAL 1600000
#define N_NODES 50000

#define FSCALE     0.17677669529663687f  // 1/sqrt(32)
#define FINV_SQRT3 0.57735026918962576f  // 1/sqrt(3)

__device__ int    g_counts[N_NODES];
__device__ int    g_cursor[N_NODES];
__device__ int    g_offsets[N_NODES + 1];
__device__ int    g_sender[E_TOTAL];            // slot -> sender
__device__ float4 g_rec[(size_t)E_TOTAL * 3];   // slot -> {h0..3, h4..7, ef}
__device__ float4 g_nodes4[N_NODES * 8];        // node -> 8 x {s_m, v_m0, v_m1, v_m2}

__global__ void k_zero_counts() {
    int i = blockIdx.x * blockDim.x + threadIdx.x;
    if (i < N_NODES) g_counts[i] = 0;
}

// Transpose node_feats rows into per-m float4 {s, v0, v1, v2}
__global__ void k_prep_nodes(const float* __restrict__ node_feats) {
    int i = blockIdx.x * blockDim.x + threadIdx.x;   // node*8 + m
    if (i >= N_NODES * 8) return;
    int node = i >> 3;
    int m    = i & 7;
    const float* nf = node_feats + node * 32;
    g_nodes4[i] = make_float4(__ldg(nf + m),
                              __ldg(nf + 8 + 3 * m),
                              __ldg(nf + 9 + 3 * m),
                              __ldg(nf + 10 + 3 * m));
}

__global__ void k_count(const int* __restrict__ receivers) {
    int e = blockIdx.x * blockDim.x + threadIdx.x;
    if (e < E_TOTAL) atomicAdd(&g_counts[__ldg(&receivers[e])], 1);
}

__global__ void k_scan() {
    __shared__ int ssum[1024];
    const int CH = (N_NODES + 1023) / 1024;  // 49
    int t = threadIdx.x;
    int base = t * CH;
    int c[CH];
    #pragma unroll
    for (int i = 0; i < CH; i++) {
        int idx = base + i;
        c[i] = (idx < N_NODES) ? __ldg(&g_counts[idx]) : 0;
    }
    int s = 0;
    #pragma unroll
    for (int i = 0; i < CH; i++) s += c[i];
    ssum[t] = s;
    __syncthreads();
    for (int off = 1; off < 1024; off <<= 1) {
        int v = (t >= off) ? ssum[t - off] : 0;
        __syncthreads();
        ssum[t] += v;
        __syncthreads();
    }
    int run = (t > 0) ? ssum[t - 1] : 0;
    #pragma unroll
    for (int i = 0; i < CH; i++) {
        int idx = base + i;
        if (idx < N_NODES) {
            g_offsets[idx] = run;
            g_cursor[idx]  = run;
            run += c[i];
        }
    }
    if (t == 1023) g_offsets[N_NODES] = ssum[1023];
}

// Fused fill + hidden MLP: coalesced reads in edge order, scattered 52B writes.
__global__ __launch_bounds__(256) void k_fill_hidden(
    const int*    __restrict__ senders,
    const int*    __restrict__ receivers,
    const float4* __restrict__ radial,
    const float4* __restrict__ edge_features,
    const float*  __restrict__ w1)
{
    __shared__ float sw1[64];
    int t = threadIdx.x;
    if (t < 64) sw1[t] = w1[t];
    __syncthreads();

    int e = blockIdx.x * 256 + t;
    if (e >= E_TOTAL) return;

    float4 r0 = __ldg(&radial[2 * e]);
    float4 r1 = __ldg(&radial[2 * e + 1]);
    float4 ef = __ldg(&edge_features[e]);
    int   snd = __ldg(&senders[e]);
    int   rcv = __ldg(&receivers[e]);

    float r[8] = {r0.x, r0.y, r0.z, r0.w, r1.x, r1.y, r1.z, r1.w};
    float h[8];
    #pragma unroll
    for (int j = 0; j < 8; j++) {
        float acc = 0.f;
        #pragma unroll
        for (int i = 0; i < 8; i++) acc = fmaf(r[i], sw1[i * 8 + j], acc);
        h[j] = acc * (FSCALE / (1.f + __expf(-acc)));
    }

    int pos = atomicAdd(&g_cursor[rcv], 1);
    g_sender[pos]        = snd;
    g_rec[3 * pos]       = make_float4(h[0], h[1], h[2], h[3]);
    g_rec[3 * pos + 1]   = make_float4(h[4], h[5], h[6], h[7]);
    g_rec[3 * pos + 2]   = ef;
}

// One block (4 warps) per node; warp takes 1/4 of segment.
// Lane l (<24) owns scal[l], vec[l][0..2]. 5 loads/edge, no shuffles.
#define EDGE_BODY(KK)                                                         \
    {                                                                         \
        int snd = g_sender[(KK)];                                             \
        float4 nd = g_nodes4[snd * 8 + mm];                                   \
        float4 h0 = g_rec[3 * (KK)];                                          \
        float4 h1 = g_rec[3 * (KK) + 1];                                      \
        float4 ef = g_rec[3 * (KK) + 2];                                      \
        float s = nd.x, v0 = nd.y, v1 = nd.z, v2 = nd.w;                      \
        float e0 = ef.x, e1x = ef.y, e1y = ef.z, e1z = ef.w;                  \
        float wa, wb;                                                         \
        wa = fmaf(h0.x, w2A[0], fmaf(h0.y, w2A[1],                            \
             fmaf(h0.z, w2A[2], h0.w * w2A[3])));                             \
        wa = fmaf(h1.x, w2A[4], fmaf(h1.y, w2A[5],                            \
             fmaf(h1.z, w2A[6], fmaf(h1.w, w2A[7], wa))));                    \
        wb = fmaf(h0.x, w2B[0], fmaf(h0.y, w2B[1],                            \
             fmaf(h0.z, w2B[2], h0.w * w2B[3])));                             \
        wb = fmaf(h1.x, w2B[4], fmaf(h1.y, w2B[5],                            \
             fmaf(h1.z, w2B[6], fmaf(h1.w, w2B[7], wb))));                    \
        float eS   = g0 ? 1.f : (g1 ? e0 : 0.f);                              \
        float dsel = g2 ? 1.f : 0.f;                                          \
        float dot  = fmaf(v0, e1x, fmaf(v1, e1y, v2 * e1z));                  \
        float scal_inner = fmaf(s, eS, dot * dsel);                           \
        float fV  = g0 ? 1.f : (g2 ? e0 : 0.f);                               \
        float sfs = s * fS;                                                   \
        float i0 = fmaf(v0, fV, sfs * e1x);                                   \
        float i1 = fmaf(v1, fV, sfs * e1y);                                   \
        float i2 = fmaf(v2, fV, sfs * e1z);                                   \
        acc_s  = fmaf(scal_inner, wa, acc_s);                                 \
        acc_v0 = fmaf(i0, wb, acc_v0);                                        \
        acc_v1 = fmaf(i1, wb, acc_v1);                                        \
        acc_v2 = fmaf(i2, wb, acc_v2);                                        \
    }

__global__ __launch_bounds__(128) void k_gather(
    const float* __restrict__ w2,
    float*       __restrict__ out)
{
    __shared__ float red[4][96];

    int node = blockIdx.x;
    int lane = threadIdx.x & 31;
    int wi   = threadIdx.x >> 5;
    int mm   = lane & 7;

    bool g0 = lane < 8;
    bool g1 = (lane >= 8) && (lane < 16);
    bool g2 = (lane >= 16) && (lane < 24);
    int  cA = (lane < 24) ? lane : 0;
    float fS = g1 ? 1.f : 0.f;
    float sA = g2 ? FINV_SQRT3 : 1.f;

    float w2A[8], w2B[8];
    #pragma unroll
    for (int j = 0; j < 8; j++) {
        w2A[j] = __ldg(&w2[j * 48 + cA]) * sA;
        w2B[j] = __ldg(&w2[j * 48 + 24 + cA]);
    }

    int beg = g_offsets[node];
    int end = g_offsets[node + 1];
    int len = end - beg;
    int lo  = beg + (len * wi)       / 4;
    int hi  = beg + (len * (wi + 1)) / 4;

    float acc_s = 0.f, acc_v0 = 0.f, acc_v1 = 0.f, acc_v2 = 0.f;

    int k = lo;
    #pragma unroll 1
    for (; k + 1 < hi; k += 2) {
        EDGE_BODY(k)
        EDGE_BODY(k + 1)
    }
    if (k < hi) EDGE_BODY(k)

    if (lane < 24) {
        red[wi][lane]              = acc_s;
        red[wi][24 + 3 * lane]     = acc_v0;
        red[wi][24 + 3 * lane + 1] = acc_v1;
        red[wi][24 + 3 * lane + 2] = acc_v2;
    }
    __syncthreads();

    int t = threadIdx.x;
    if (t < 96) {
        out[(size_t)node * 96 + t] = red[0][t] + red[1][t] + red[2][t] + red[3][t];
    }
}

extern "C" void kernel_launch(void* const* d_in, const int* in_sizes, int n_in,
                              void* d_out, int out_size) {
    const float*  node_feats    = (const float*)d_in[0];
    const float4* edge_features = (const float4*)d_in[1];
    const float4* radial        = (const float4*)d_in[2];
    const float*  w1            = (const float*)d_in[3];
    const float*  w2            = (const float*)d_in[4];
    const int*    senders       = (const int*)d_in[5];
    const int*    receivers     = (const int*)d_in[6];
    float* out = (float*)d_out;

    k_zero_counts<<<(N_NODES + 511) / 512, 512>>>();
    k_prep_nodes<<<(N_NODES * 8 + 255) / 256, 256>>>(node_feats);
    k_count<<<(E_TOTAL + 511) / 512, 512>>>(receivers);
    k_scan<<<1, 1024>>>();
    k_fill_hidden<<<(E_TOTAL + 255) / 256, 256>>>(senders, receivers, radial,
                                                  edge_features, w1);
    k_gather<<<N_NODES, 128>>>(w2, out);
}

// round 11
// speedup vs baseline: 2.5912x; 1.2339x over previous
#include <cuda_runtime.h>

#define E_TOTAL 1600000
#define N_NODES 50000

#define FSCALE     0.17677669529663687f  // 1/sqrt(32)
#define FINV_SQRT3 0.57735026918962576f  // 1/sqrt(3)

#define SCAN_B   512
#define SCAN_NB  ((N_NODES + SCAN_B - 1) / SCAN_B)   // 98

__device__ int    g_counts[N_NODES];
__device__ int    g_cursor[N_NODES];
__device__ int    g_offsets[N_NODES + 1];
__device__ int    g_scantmp[N_NODES];
__device__ int    g_bsums[SCAN_NB];
__device__ int    g_bbase[SCAN_NB];
__device__ int    g_sender[E_TOTAL];            // slot -> sender
__device__ float4 g_rec[(size_t)E_TOTAL * 3];   // slot -> {h0..3, h4..7, ef}
__device__ float4 g_nodes4[N_NODES * 8];        // node -> 8 x {s_m, v_m0, v_m1, v_m2}

__global__ void k_zero_counts() {
    int i = blockIdx.x * blockDim.x + threadIdx.x;
    if (i < N_NODES) g_counts[i] = 0;
}

// Transpose node_feats rows into per-m float4 {s, v0, v1, v2}
__global__ void k_prep_nodes(const float* __restrict__ node_feats) {
    int i = blockIdx.x * blockDim.x + threadIdx.x;   // node*8 + m
    if (i >= N_NODES * 8) return;
    int node = i >> 3;
    int m    = i & 7;
    const float* nf = node_feats + node * 32;
    g_nodes4[i] = make_float4(__ldg(nf + m),
                              __ldg(nf + 8 + 3 * m),
                              __ldg(nf + 9 + 3 * m),
                              __ldg(nf + 10 + 3 * m));
}

__global__ void k_count(const int* __restrict__ receivers) {
    int e = blockIdx.x * blockDim.x + threadIdx.x;
    if (e < E_TOTAL) atomicAdd(&g_counts[__ldg(&receivers[e])], 1);
}

// Pass 1: per-block inclusive scan of counts
__global__ __launch_bounds__(SCAN_B) void k_scan1() {
    __shared__ int sh[SCAN_B];
    int t   = threadIdx.x;
    int idx = blockIdx.x * SCAN_B + t;
    int v   = (idx < N_NODES) ? g_counts[idx] : 0;
    sh[t] = v;
    __syncthreads();
    for (int off = 1; off < SCAN_B; off <<= 1) {
        int u = (t >= off) ? sh[t - off] : 0;
        __syncthreads();
        sh[t] += u;
        __syncthreads();
    }
    if (idx < N_NODES) g_scantmp[idx] = sh[t];
    if (t == SCAN_B - 1) g_bsums[blockIdx.x] = sh[t];
}

// Pass 2: single small block scans the 98 block sums -> exclusive bases
__global__ __launch_bounds__(128) void k_scan2() {
    __shared__ int sh[128];
    int t = threadIdx.x;
    int v = (t < SCAN_NB) ? g_bsums[t] : 0;
    sh[t] = v;
    __syncthreads();
    for (int off = 1; off < 128; off <<= 1) {
        int u = (t >= off) ? sh[t - off] : 0;
        __syncthreads();
        sh[t] += u;
        __syncthreads();
    }
    if (t < SCAN_NB) g_bbase[t] = sh[t] - v;   // exclusive base
    if (t == SCAN_NB - 1) g_offsets[N_NODES] = sh[t];
}

// Pass 3: global exclusive offsets + cursor
__global__ __launch_bounds__(SCAN_B) void k_scan3() {
    int idx = blockIdx.x * SCAN_B + threadIdx.x;
    if (idx < N_NODES) {
        int off = g_bbase[blockIdx.x] + g_scantmp[idx] - g_counts[idx];
        g_offsets[idx] = off;
        g_cursor[idx]  = off;
    }
}

// Fused fill + hidden MLP: coalesced reads in edge order, scattered 52B writes.
__global__ __launch_bounds__(256) void k_fill_hidden(
    const int*    __restrict__ senders,
    const int*    __restrict__ receivers,
    const float4* __restrict__ radial,
    const float4* __restrict__ edge_features,
    const float*  __restrict__ w1)
{
    __shared__ float sw1[64];
    int t = threadIdx.x;
    if (t < 64) sw1[t] = w1[t];
    __syncthreads();

    int e = blockIdx.x * 256 + t;
    if (e >= E_TOTAL) return;

    float4 r0 = __ldg(&radial[2 * e]);
    float4 r1 = __ldg(&radial[2 * e + 1]);
    float4 ef = __ldg(&edge_features[e]);
    int   snd = __ldg(&senders[e]);
    int   rcv = __ldg(&receivers[e]);

    float r[8] = {r0.x, r0.y, r0.z, r0.w, r1.x, r1.y, r1.z, r1.w};
    float h[8];
    #pragma unroll
    for (int j = 0; j < 8; j++) {
        float acc = 0.f;
        #pragma unroll
        for (int i = 0; i < 8; i++) acc = fmaf(r[i], sw1[i * 8 + j], acc);
        h[j] = acc * (FSCALE / (1.f + __expf(-acc)));
    }

    int pos = atomicAdd(&g_cursor[rcv], 1);
    g_sender[pos]        = snd;
    g_rec[3 * pos]       = make_float4(h[0], h[1], h[2], h[3]);
    g_rec[3 * pos + 1]   = make_float4(h[4], h[5], h[6], h[7]);
    g_rec[3 * pos + 2]   = ef;
}

// One block (4 warps) per node; warp takes 1/4 of segment.
// Lane l (<24) owns scal[l], vec[l][0..2]. 5 loads/edge, no shuffles.
#define EDGE_BODY(KK)                                                         \
    {                                                                         \
        int snd = g_sender[(KK)];                                             \
        float4 nd = g_nodes4[snd * 8 + mm];                                   \
        float4 h0 = g_rec[3 * (KK)];                                          \
        float4 h1 = g_rec[3 * (KK) + 1];                                      \
        float4 ef = g_rec[3 * (KK) + 2];                                      \
        float s = nd.x, v0 = nd.y, v1 = nd.z, v2 = nd.w;                      \
        float e0 = ef.x, e1x = ef.y, e1y = ef.z, e1z = ef.w;                  \
        float wa, wb;                                                         \
        wa = fmaf(h0.x, w2A[0], fmaf(h0.y, w2A[1],                            \
             fmaf(h0.z, w2A[2], h0.w * w2A[3])));                             \
        wa = fmaf(h1.x, w2A[4], fmaf(h1.y, w2A[5],                            \
             fmaf(h1.z, w2A[6], fmaf(h1.w, w2A[7], wa))));                    \
        wb = fmaf(h0.x, w2B[0], fmaf(h0.y, w2B[1],                            \
             fmaf(h0.z, w2B[2], h0.w * w2B[3])));                             \
        wb = fmaf(h1.x, w2B[4], fmaf(h1.y, w2B[5],                            \
             fmaf(h1.z, w2B[6], fmaf(h1.w, w2B[7], wb))));                    \
        float eS   = g0 ? 1.f : (g1 ? e0 : 0.f);                              \
        float dsel = g2 ? 1.f : 0.f;                                          \
        float dot  = fmaf(v0, e1x, fmaf(v1, e1y, v2 * e1z));                  \
        float scal_inner = fmaf(s, eS, dot * dsel);                           \
        float fV  = g0 ? 1.f : (g2 ? e0 : 0.f);                               \
        float sfs = s * fS;                                                   \
        float i0 = fmaf(v0, fV, sfs * e1x);                                   \
        float i1 = fmaf(v1, fV, sfs * e1y);                                   \
        float i2 = fmaf(v2, fV, sfs * e1z);                                   \
        acc_s  = fmaf(scal_inner, wa, acc_s);                                 \
        acc_v0 = fmaf(i0, wb, acc_v0);                                        \
        acc_v1 = fmaf(i1, wb, acc_v1);                                        \
        acc_v2 = fmaf(i2, wb, acc_v2);                                        \
    }

__global__ __launch_bounds__(128) void k_gather(
    const float* __restrict__ w2,
    float*       __restrict__ out)
{
    __shared__ float red[4][96];

    int node = blockIdx.x;
    int lane = threadIdx.x & 31;
    int wi   = threadIdx.x >> 5;
    int mm   = lane & 7;

    bool g0 = lane < 8;
    bool g1 = (lane >= 8) && (lane < 16);
    bool g2 = (lane >= 16) && (lane < 24);
    int  cA = (lane < 24) ? lane : 0;
    float fS = g1 ? 1.f : 0.f;
    float sA = g2 ? FINV_SQRT3 : 1.f;

    float w2A[8], w2B[8];
    #pragma unroll
    for (int j = 0; j < 8; j++) {
        w2A[j] = __ldg(&w2[j * 48 + cA]) * sA;
        w2B[j] = __ldg(&w2[j * 48 + 24 + cA]);
    }

    int beg = g_offsets[node];
    int end = g_offsets[node + 1];
    int len = end - beg;
    int lo  = beg + (len * wi)       / 4;
    int hi  = beg + (len * (wi + 1)) / 4;

    float acc_s = 0.f, acc_v0 = 0.f, acc_v1 = 0.f, acc_v2 = 0.f;

    int k = lo;
    #pragma unroll 1
    for (; k + 1 < hi; k += 2) {
        EDGE_BODY(k)
        EDGE_BODY(k + 1)
    }
    if (k < hi) EDGE_BODY(k)

    if (lane < 24) {
        red[wi][lane]              = acc_s;
        red[wi][24 + 3 * lane]     = acc_v0;
        red[wi][24 + 3 * lane + 1] = acc_v1;
        red[wi][24 + 3 * lane + 2] = acc_v2;
    }
    __syncthreads();

    int t = threadIdx.x;
    if (t < 96) {
        out[(size_t)node * 96 + t] = red[0][t] + red[1][t] + red[2][t] + red[3][t];
    }
}

extern "C" void kernel_launch(void* const* d_in, const int* in_sizes, int n_in,
                              void* d_out, int out_size) {
    const float*  node_feats    = (const float*)d_in[0];
    const float4* edge_features = (const float4*)d_in[1];
    const float4* radial        = (const float4*)d_in[2];
    const float*  w1            = (const float*)d_in[3];
    const float*  w2            = (const float*)d_in[4];
    const int*    senders       = (const int*)d_in[5];
    const int*    receivers     = (const int*)d_in[6];
    float* out = (float*)d_out;

    k_zero_counts<<<(N_NODES + 511) / 512, 512>>>();
    k_prep_nodes<<<(N_NODES * 8 + 255) / 256, 256>>>(node_feats);
    k_count<<<(E_TOTAL + 511) / 512, 512>>>(receivers);
    k_scan1<<<SCAN_NB, SCAN_B>>>();
    k_scan2<<<1, 128>>>();
    k_scan3<<<SCAN_NB, SCAN_B>>>();
    k_fill_hidden<<<(E_TOTAL + 255) / 256, 256>>>(senders, receivers, radial,
                                                  edge_features, w1);
    k_gather<<<N_NODES, 128>>>(w2, out);
}